// round 6
// baseline (speedup 1.0000x reference)
#include <cuda_runtime.h>
#include <cuda_fp16.h>
#include <cstdint>
#include <cstddef>

// out[256,11008] = x[256,4096] @ W[11008,4096]^T * scale + bias, W ternary i32.
// fp16 mma.sync m16n8k16 single pass, fp32 accum (rel_err ~2e-4 << 1e-3).
// BM=128 BN=160 BK=64, 256 threads / 8 warps in 2(m)x4(n) grid, warp tile
// 64x40. 138 CTAs (single wave). W: LDG.128 -> reg ternary->fp16 -> STS.64.
// A: cp.async fp16. One __syncthreads per iter, 2 SMEM stages.

#define M_TOK   256
#define K_DIM   4096
#define N_DIM   11008
#define BM      128
#define BN      160
#define BK      64
#define KITERS  (K_DIM / BK)          // 64
#define THREADS 256
#define N_TILES 69
#define GRID    (2 * N_TILES)         // 138

#define ROWB     144                  // row pad: conflict-free ldmatrix
#define A_OFF    0                    // 128 x 144B = 18432
#define B_OFF    18432                // 160 x 144B = 23040
#define STAGE_BYTES 41472
#define SMEM_ALLOC (2 * STAGE_BYTES)  // 82944

__device__ __half g_xh[M_TOK * K_DIM];

// ---------------- asm helpers ----------------
__device__ __forceinline__ uint32_t smem_u32(const void* p) {
    uint32_t a;
    asm("{ .reg .u64 t; cvta.to.shared.u64 t, %1; cvt.u32.u64 %0, t; }"
        : "=r"(a) : "l"(p));
    return a;
}
__device__ __forceinline__ void cp16(uint32_t dst, const void* src) {
    asm volatile("cp.async.cg.shared.global [%0], [%1], 16;"
        :: "r"(dst), "l"(src) : "memory");
}
#define CP_COMMIT() asm volatile("cp.async.commit_group;" ::: "memory")
#define CP_WAIT0()  asm volatile("cp.async.wait_group 0;" ::: "memory")

__device__ __forceinline__ void ldsm4(uint32_t* r, uint32_t addr) {
    asm volatile("ldmatrix.sync.aligned.m8n8.x4.shared.b16 {%0,%1,%2,%3}, [%4];"
        : "=r"(r[0]), "=r"(r[1]), "=r"(r[2]), "=r"(r[3]) : "r"(addr));
}
__device__ __forceinline__ void ldsm2(uint32_t* r, uint32_t addr) {
    asm volatile("ldmatrix.sync.aligned.m8n8.x2.shared.b16 {%0,%1}, [%2];"
        : "=r"(r[0]), "=r"(r[1]) : "r"(addr));
}
__device__ __forceinline__ void mma_f16(float* c, const uint32_t* a,
                                        const uint32_t* b) {
    asm volatile(
        "mma.sync.aligned.m16n8k16.row.col.f32.f16.f16.f32 "
        "{%0,%1,%2,%3}, {%4,%5,%6,%7}, {%8,%9}, {%0,%1,%2,%3};"
        : "+f"(c[0]), "+f"(c[1]), "+f"(c[2]), "+f"(c[3])
        : "r"(a[0]), "r"(a[1]), "r"(a[2]), "r"(a[3]), "r"(b[0]), "r"(b[1]));
}
__device__ __forceinline__ uint32_t w2h(int w0, int w1) {
    uint32_t l = (w0 == 0) ? 0u : ((w0 > 0) ? 0x3C00u : 0xBC00u);
    uint32_t h = (w1 == 0) ? 0u : ((w1 > 0) ? 0x3C00u : 0xBC00u);
    return l | (h << 16);
}

// ---------------- x convert pre-kernel ----------------
__global__ void conv_x_kernel(const float* __restrict__ x) {
    int i = (blockIdx.x * blockDim.x + threadIdx.x) << 2;
    float4 v = *reinterpret_cast<const float4*>(x + i);
    __half2* ph = reinterpret_cast<__half2*>(g_xh + i);
    ph[0] = __floats2half2_rn(v.x, v.y);
    ph[1] = __floats2half2_rn(v.z, v.w);
}

// ---------------- main GEMM ----------------
__global__ void __launch_bounds__(THREADS, 1)
bitnet_gemm_kernel(const int* __restrict__ qw, const float* __restrict__ scale,
                   const float* __restrict__ bias, float* __restrict__ out) {
    extern __shared__ char smem[];
    const uint32_t su = smem_u32(smem);

    const int tid = threadIdx.x, wid = tid >> 5, lane = tid & 31;
    const int n_idx = blockIdx.x >> 1, m_idx = blockIdx.x & 1;
    const int n0 = n_idx * BN, m0 = m_idx * BM;
    const int n_sz = (n_idx == N_TILES - 1) ? (N_DIM - n0) : BN;   // 160 or 128

    const int warp_m = wid & 1;        // 2 m-groups, 64 rows each
    const int warp_n = wid >> 1;       // 4 n-groups, 40 cols each
    const int nbase = warp_n * 40;
    int ntiles = (n_sz - nbase) >> 3;
    if (ntiles > 5) ntiles = 5;
    if (ntiles < 0) ntiles = 0;

    // ldmatrix offsets
    const uint32_t a_off = (uint32_t)((warp_m * 64 + (lane & 15)) * ROWB +
                                      ((lane >> 4) << 4));
    // x4 B: lanes 0-7 nt rows+0B, 8-15 nt rows+16B, 16-23 nt+1 rows, 24-31 +16B
    const uint32_t b_off4 = (uint32_t)((nbase + ((lane >> 4) << 3) + (lane & 7)) * ROWB +
                                       (((lane >> 3) & 1) << 4));
    const uint32_t b_off2 = (uint32_t)((nbase + 32 + (lane & 7)) * ROWB +
                                       (((lane >> 3) & 1) << 4));

    // W LDG: 2560 chunks (160 rows x 16), 10/thread; kc = tid&15 fixed,
    // row_j = (tid>>4) + 16j. One base + int offsets (register-lean).
    const int w_kc = tid & 15, w_row0 = tid >> 4;
    const int* wbase = qw + (size_t)n0 * K_DIM + w_kc * 4;
    int woff[10];
#pragma unroll
    for (int j = 0; j < 10; ++j) {
        int row = w_row0 + 16 * j;
        int srow = (row < n_sz) ? row : 0;     // clamp (unread if OOB)
        woff[j] = srow * K_DIM;
    }
    // A cp.async: 1024 chunks (128 rows x 8), 4/thread; kc = tid&7 fixed,
    // row_j = (tid>>3) + 32j.
    const int a_kc = tid & 7, a_row0 = tid >> 3;
    const __half* abase = g_xh + (size_t)(m0 + a_row0) * K_DIM + a_kc * 8;
    const uint32_t ad0 = (uint32_t)(a_row0 * ROWB + a_kc * 16);

    float acc[4][5][4];
#pragma unroll
    for (int mt = 0; mt < 4; ++mt)
#pragma unroll
        for (int nt = 0; nt < 5; ++nt)
#pragma unroll
            for (int r = 0; r < 4; ++r) acc[mt][nt][r] = 0.0f;

    int wreg[40];

    auto ldgW = [&](int k0) {
#pragma unroll
        for (int j = 0; j < 10; ++j) {
            asm volatile("ld.global.cs.v4.u32 {%0,%1,%2,%3}, [%4];"
                : "=r"(*(uint32_t*)&wreg[4*j]),   "=r"(*(uint32_t*)&wreg[4*j+1]),
                  "=r"(*(uint32_t*)&wreg[4*j+2]), "=r"(*(uint32_t*)&wreg[4*j+3])
                : "l"(wbase + woff[j] + k0));
        }
    };
    auto cpA = [&](int s, int k0) {
        const uint32_t st = su + (uint32_t)(s * STAGE_BYTES);
#pragma unroll
        for (int j = 0; j < 4; ++j)
            cp16(st + A_OFF + ad0 + (uint32_t)(j * 32 * ROWB),
                 abase + (size_t)j * 32 * K_DIM + k0);
    };

    // ---- prologue ----
    ldgW(0);
    cpA(0, 0);
    CP_COMMIT();

#pragma unroll 1
    for (int it = 0; it < KITERS; ++it) {
        const int cur = it & 1;
        const uint32_t st = su + (uint32_t)(cur * STAGE_BYTES);

        // STS W(it) from regs (ternary -> fp16)
#pragma unroll
        for (int j = 0; j < 10; ++j) {
            int row = w_row0 + 16 * j;
            uint32_t p0 = w2h(wreg[4*j],   wreg[4*j+1]);
            uint32_t p1 = w2h(wreg[4*j+2], wreg[4*j+3]);
            asm volatile("st.shared.v2.b32 [%0], {%1,%2};"
                :: "r"(st + B_OFF + (uint32_t)(row * ROWB + w_kc * 8)),
                   "r"(p0), "r"(p1) : "memory");
        }
        if (it + 1 < KITERS) ldgW((it + 1) * BK);   // covered by compute phase
        CP_WAIT0();                                 // A(it) landed
        __syncthreads();
        if (it + 1 < KITERS) { cpA(cur ^ 1, (it + 1) * BK); CP_COMMIT(); }

        // ---- compute BK=64: 4 k16 steps ----
#pragma unroll
        for (int ks = 0; ks < 4; ++ks) {
            const uint32_t ksb = (uint32_t)(ks * 32);
            uint32_t b[5][2];
            if (ntiles == 5) {
                ldsm4(&b[0][0], st + B_OFF + b_off4 + ksb);                 // nt0,1
                ldsm4(&b[2][0], st + B_OFF + b_off4 + 16 * ROWB + ksb);     // nt2,3
                ldsm2(&b[4][0], st + B_OFF + b_off2 + ksb);                 // nt4
            } else {
#pragma unroll
                for (int nt = 0; nt < 5; ++nt)
                    if (nt < ntiles)
                        ldsm2(&b[nt][0], st + B_OFF +
                              (uint32_t)((nbase + nt * 8 + (lane & 7)) * ROWB +
                                         (((lane >> 3) & 1) << 4)) + ksb);
            }
            uint32_t a[4][4];
#pragma unroll
            for (int mt = 0; mt < 4; ++mt)
                ldsm4(a[mt], st + A_OFF + a_off + (uint32_t)(mt * 16 * ROWB) + ksb);
#pragma unroll
            for (int mt = 0; mt < 4; ++mt)
#pragma unroll
                for (int nt = 0; nt < 5; ++nt)
                    if (nt < ntiles) mma_f16(acc[mt][nt], a[mt], b[nt]);
        }
    }

    // ---- epilogue: scale/bias + store ----
    const int row_base = m0 + warp_m * 64 + (lane >> 2);
    const int col_base = n0 + nbase + ((lane & 3) << 1);
#pragma unroll
    for (int mt = 0; mt < 4; ++mt) {
#pragma unroll
        for (int nt = 0; nt < 5; ++nt) {
            if (nt < ntiles) {
                int col = col_base + nt * 8;
                float2 sc = *reinterpret_cast<const float2*>(scale + col);
                float2 bs = *reinterpret_cast<const float2*>(bias + col);
                int r0 = row_base + mt * 16;
                float2 o0, o1;
                o0.x = acc[mt][nt][0] * sc.x + bs.x;
                o0.y = acc[mt][nt][1] * sc.y + bs.y;
                o1.x = acc[mt][nt][2] * sc.x + bs.x;
                o1.y = acc[mt][nt][3] * sc.y + bs.y;
                *reinterpret_cast<float2*>(out + (size_t)r0 * N_DIM + col) = o0;
                *reinterpret_cast<float2*>(out + (size_t)(r0 + 8) * N_DIM + col) = o1;
            }
        }
    }
}

// ---------------- launch ----------------
extern "C" void kernel_launch(void* const* d_in, const int* in_sizes, int n_in,
                              void* d_out, int out_size) {
    const float* x = nullptr; const int* qw = nullptr;
    const float* scale = nullptr; const float* bias = nullptr;
    for (int i = 0; i < n_in; ++i) {
        if (in_sizes[i] == M_TOK * K_DIM) x = (const float*)d_in[i];
        else if (in_sizes[i] == N_DIM * K_DIM) qw = (const int*)d_in[i];
        else if (in_sizes[i] == N_DIM) {
            if (!scale) scale = (const float*)d_in[i];
            else bias = (const float*)d_in[i];
        }
    }
    float* out = (float*)d_out;

    cudaFuncSetAttribute(bitnet_gemm_kernel,
                         cudaFuncAttributeMaxDynamicSharedMemorySize, SMEM_ALLOC);

    conv_x_kernel<<<(M_TOK * K_DIM) / (256 * 4), 256>>>(x);
    bitnet_gemm_kernel<<<GRID, THREADS, SMEM_ALLOC>>>(qw, scale, bias, out);
}

// round 7
// speedup vs baseline: 1.0685x; 1.0685x over previous
#include <cuda_runtime.h>
#include <cuda_fp16.h>
#include <cstdint>
#include <cstddef>

// out[256,11008] = x[256,4096] @ W[11008,4096]^T * scale + bias, W ternary i32.
// fp16 mma.sync m16n8k16 single pass, fp32 accum (rel_err ~2e-4 << 1e-3).
// BM=128 BN=80 BK=64, 256 threads / 8 warps (4m x 2n, warp tile 32x40),
// 276 CTAs, 2 CTAs/SM (independent barrier domains -> latency overlap).
// W: LDG.128 -> reg ternary->fp16 -> STS.64. A: cp.async fp16.
// One __syncthreads per iter, 2 SMEM stages.

#define M_TOK   256
#define K_DIM   4096
#define N_DIM   11008
#define BM      128
#define BN      80
#define BK      64
#define KITERS  (K_DIM / BK)          // 64
#define THREADS 256
#define N_TILES 138                   // 138*80 = 11040 >= 11008
#define GRID    (2 * N_TILES)         // 276

#define ROWB     144                  // row pad: conflict-free ldmatrix
#define A_OFF    0                    // 128 x 144B = 18432
#define B_OFF    18432                // 80 x 144B = 11520
#define STAGE_BYTES 29952
#define SMEM_ALLOC (2 * STAGE_BYTES)  // 59904

__device__ __half g_xh[M_TOK * K_DIM];

// ---------------- asm helpers ----------------
__device__ __forceinline__ uint32_t smem_u32(const void* p) {
    uint32_t a;
    asm("{ .reg .u64 t; cvta.to.shared.u64 t, %1; cvt.u32.u64 %0, t; }"
        : "=r"(a) : "l"(p));
    return a;
}
__device__ __forceinline__ void cp16(uint32_t dst, const void* src) {
    asm volatile("cp.async.cg.shared.global [%0], [%1], 16;"
        :: "r"(dst), "l"(src) : "memory");
}
#define CP_COMMIT() asm volatile("cp.async.commit_group;" ::: "memory")
#define CP_WAIT0()  asm volatile("cp.async.wait_group 0;" ::: "memory")

__device__ __forceinline__ void ldsm4(uint32_t* r, uint32_t addr) {
    asm volatile("ldmatrix.sync.aligned.m8n8.x4.shared.b16 {%0,%1,%2,%3}, [%4];"
        : "=r"(r[0]), "=r"(r[1]), "=r"(r[2]), "=r"(r[3]) : "r"(addr));
}
__device__ __forceinline__ void ldsm2(uint32_t* r, uint32_t addr) {
    asm volatile("ldmatrix.sync.aligned.m8n8.x2.shared.b16 {%0,%1}, [%2];"
        : "=r"(r[0]), "=r"(r[1]) : "r"(addr));
}
__device__ __forceinline__ void mma_f16(float* c, const uint32_t* a,
                                        const uint32_t* b) {
    asm volatile(
        "mma.sync.aligned.m16n8k16.row.col.f32.f16.f16.f32 "
        "{%0,%1,%2,%3}, {%4,%5,%6,%7}, {%8,%9}, {%0,%1,%2,%3};"
        : "+f"(c[0]), "+f"(c[1]), "+f"(c[2]), "+f"(c[3])
        : "r"(a[0]), "r"(a[1]), "r"(a[2]), "r"(a[3]), "r"(b[0]), "r"(b[1]));
}
__device__ __forceinline__ uint32_t w2h(int w0, int w1) {
    uint32_t l = (w0 == 0) ? 0u : ((w0 > 0) ? 0x3C00u : 0xBC00u);
    uint32_t h = (w1 == 0) ? 0u : ((w1 > 0) ? 0x3C00u : 0xBC00u);
    return l | (h << 16);
}

// ---------------- x convert pre-kernel ----------------
__global__ void conv_x_kernel(const float* __restrict__ x) {
    int i = (blockIdx.x * blockDim.x + threadIdx.x) << 2;
    float4 v = *reinterpret_cast<const float4*>(x + i);
    __half2* ph = reinterpret_cast<__half2*>(g_xh + i);
    ph[0] = __floats2half2_rn(v.x, v.y);
    ph[1] = __floats2half2_rn(v.z, v.w);
}

// ---------------- main GEMM ----------------
__global__ void __launch_bounds__(THREADS, 2)
bitnet_gemm_kernel(const int* __restrict__ qw, const float* __restrict__ scale,
                   const float* __restrict__ bias, float* __restrict__ out) {
    extern __shared__ char smem[];
    const uint32_t su = smem_u32(smem);

    const int tid = threadIdx.x, wid = tid >> 5, lane = tid & 31;
    const int n_idx = blockIdx.x >> 1, m_idx = blockIdx.x & 1;
    const int n0 = n_idx * BN, m0 = m_idx * BM;
    const int n_sz = (n_idx == N_TILES - 1) ? (N_DIM - n0) : BN;   // 80 or 48

    const int warp_m = wid & 3;        // 4 m-groups, 32 rows each
    const int warp_n = wid >> 2;       // 2 n-groups, 40 cols each
    const int nbase = warp_n * 40;
    int ntiles = (n_sz - nbase) >> 3;
    if (ntiles > 5) ntiles = 5;
    if (ntiles < 0) ntiles = 0;

    // ldmatrix per-thread offsets (row stride 144B)
    const uint32_t a_off = (uint32_t)((warp_m * 32 + (lane & 15)) * ROWB +
                                      ((lane >> 4) << 4));
    const uint32_t b_off = (uint32_t)((nbase + (lane & 7)) * ROWB +
                                      (((lane >> 3) & 1) << 4));

    // W LDG: 1280 16B-chunks (80 rows x 16), 5/thread; kc = tid&15 fixed,
    // row_j = (tid>>4) + 16j.
    const int w_kc = tid & 15, w_row0 = tid >> 4;
    const int* wbase = qw + (size_t)n0 * K_DIM + w_kc * 4;
    int woff[5];
#pragma unroll
    for (int j = 0; j < 5; ++j) {
        int row = w_row0 + 16 * j;
        int srow = (row < n_sz) ? row : 0;     // clamp (unread if OOB)
        woff[j] = srow * K_DIM;
    }
    // A cp.async: 1024 chunks (128 rows x 8), 4/thread; kc = tid&7 fixed,
    // row_j = (tid>>3) + 32j.
    const int a_kc = tid & 7, a_row0 = tid >> 3;
    const __half* abase = g_xh + (size_t)(m0 + a_row0) * K_DIM + a_kc * 8;
    const uint32_t ad0 = (uint32_t)(a_row0 * ROWB + a_kc * 16);

    float acc[2][5][4];
#pragma unroll
    for (int mt = 0; mt < 2; ++mt)
#pragma unroll
        for (int nt = 0; nt < 5; ++nt)
#pragma unroll
            for (int r = 0; r < 4; ++r) acc[mt][nt][r] = 0.0f;

    int wreg[20];

    auto ldgW = [&](int k0) {
#pragma unroll
        for (int j = 0; j < 5; ++j) {
            asm volatile("ld.global.cs.v4.u32 {%0,%1,%2,%3}, [%4];"
                : "=r"(*(uint32_t*)&wreg[4*j]),   "=r"(*(uint32_t*)&wreg[4*j+1]),
                  "=r"(*(uint32_t*)&wreg[4*j+2]), "=r"(*(uint32_t*)&wreg[4*j+3])
                : "l"(wbase + woff[j] + k0));
        }
    };
    auto cpA = [&](int s, int k0) {
        const uint32_t st = su + (uint32_t)(s * STAGE_BYTES);
#pragma unroll
        for (int j = 0; j < 4; ++j)
            cp16(st + A_OFF + ad0 + (uint32_t)(j * 32 * ROWB),
                 abase + (size_t)j * 32 * K_DIM + k0);
    };

    // ---- prologue ----
    ldgW(0);
    cpA(0, 0);
    CP_COMMIT();

#pragma unroll 1
    for (int it = 0; it < KITERS; ++it) {
        const int cur = it & 1;
        const uint32_t st = su + (uint32_t)(cur * STAGE_BYTES);

        // STS W(it) from regs (ternary -> fp16)
#pragma unroll
        for (int j = 0; j < 5; ++j) {
            int row = w_row0 + 16 * j;
            uint32_t p0 = w2h(wreg[4*j],   wreg[4*j+1]);
            uint32_t p1 = w2h(wreg[4*j+2], wreg[4*j+3]);
            asm volatile("st.shared.v2.b32 [%0], {%1,%2};"
                :: "r"(st + B_OFF + (uint32_t)(row * ROWB + w_kc * 8)),
                   "r"(p0), "r"(p1) : "memory");
        }
        if (it + 1 < KITERS) ldgW((it + 1) * BK);   // covered by compute phase
        CP_WAIT0();                                 // A(it) landed
        __syncthreads();
        if (it + 1 < KITERS) { cpA(cur ^ 1, (it + 1) * BK); CP_COMMIT(); }

        // ---- compute BK=64: 4 k16 steps ----
#pragma unroll
        for (int ks = 0; ks < 4; ++ks) {
            const uint32_t ksb = (uint32_t)(ks * 32);
            uint32_t b[5][2];
#pragma unroll
            for (int nt = 0; nt < 5; ++nt)
                if (nt < ntiles)
                    ldsm2(b[nt], st + B_OFF + b_off +
                          (uint32_t)(nt * 8 * ROWB) + ksb);
            uint32_t a[2][4];
#pragma unroll
            for (int mt = 0; mt < 2; ++mt)
                ldsm4(a[mt], st + A_OFF + a_off + (uint32_t)(mt * 16 * ROWB) + ksb);
#pragma unroll
            for (int mt = 0; mt < 2; ++mt)
#pragma unroll
                for (int nt = 0; nt < 5; ++nt)
                    if (nt < ntiles) mma_f16(acc[mt][nt], a[mt], b[nt]);
        }
        // single barrier per iter: next iter's STS/cpA hit the other buffer,
        // ordered against compute(it-1) by the barrier above.
    }

    // ---- epilogue: scale/bias + store ----
    const int row_base = m0 + warp_m * 32 + (lane >> 2);
    const int col_base = n0 + nbase + ((lane & 3) << 1);
#pragma unroll
    for (int mt = 0; mt < 2; ++mt) {
#pragma unroll
        for (int nt = 0; nt < 5; ++nt) {
            if (nt < ntiles) {
                int col = col_base + nt * 8;
                float2 sc = *reinterpret_cast<const float2*>(scale + col);
                float2 bs = *reinterpret_cast<const float2*>(bias + col);
                int r0 = row_base + mt * 16;
                float2 o0, o1;
                o0.x = acc[mt][nt][0] * sc.x + bs.x;
                o0.y = acc[mt][nt][1] * sc.y + bs.y;
                o1.x = acc[mt][nt][2] * sc.x + bs.x;
                o1.y = acc[mt][nt][3] * sc.y + bs.y;
                *reinterpret_cast<float2*>(out + (size_t)r0 * N_DIM + col) = o0;
                *reinterpret_cast<float2*>(out + (size_t)(r0 + 8) * N_DIM + col) = o1;
            }
        }
    }
}

// ---------------- launch ----------------
extern "C" void kernel_launch(void* const* d_in, const int* in_sizes, int n_in,
                              void* d_out, int out_size) {
    const float* x = nullptr; const int* qw = nullptr;
    const float* scale = nullptr; const float* bias = nullptr;
    for (int i = 0; i < n_in; ++i) {
        if (in_sizes[i] == M_TOK * K_DIM) x = (const float*)d_in[i];
        else if (in_sizes[i] == N_DIM * K_DIM) qw = (const int*)d_in[i];
        else if (in_sizes[i] == N_DIM) {
            if (!scale) scale = (const float*)d_in[i];
            else bias = (const float*)d_in[i];
        }
    }
    float* out = (float*)d_out;

    cudaFuncSetAttribute(bitnet_gemm_kernel,
                         cudaFuncAttributeMaxDynamicSharedMemorySize, SMEM_ALLOC);

    conv_x_kernel<<<(M_TOK * K_DIM) / (256 * 4), 256>>>(x);
    bitnet_gemm_kernel<<<GRID, THREADS, SMEM_ALLOC>>>(qw, scale, bias, out);
}

// round 8
// speedup vs baseline: 1.0891x; 1.0193x over previous
#include <cuda_runtime.h>
#include <cuda_fp16.h>
#include <cstdint>
#include <cstddef>

// out[256,11008] = x[256,4096] @ W[11008,4096]^T * scale + bias, W ternary i32.
// fp16 mma.sync m16n8k16 single pass, fp32 accum (rel_err ~2e-4 << 1e-3).
// BM=128 BN=80 BK=64. CTA = 128 threads / 4 warps (2m x 2n), warp tile 64x40.
// 276 CTAs, 2 CTAs/SM (2 barrier domains) AND ~200 regs/thread (128-thr CTAs
// allow 255-reg budget at 2 CTAs/SM). Fragment double-buffer across k16 steps.
// W: LDG.128 -> reg ternary->fp16 -> STS.64. A: cp.async fp16.

#define M_TOK   256
#define K_DIM   4096
#define N_DIM   11008
#define BM      128
#define BN      80
#define BK      64
#define KITERS  (K_DIM / BK)          // 64
#define THREADS 128
#define N_TILES 138                   // 138*80 = 11040 >= 11008
#define GRID    (2 * N_TILES)         // 276

#define ROWB     144                  // row pad: conflict-free ldmatrix
#define A_OFF    0                    // 128 x 144B = 18432
#define B_OFF    18432                // 80 x 144B = 11520
#define STAGE_BYTES 29952
#define SMEM_ALLOC (2 * STAGE_BYTES)  // 59904

__device__ __half g_xh[M_TOK * K_DIM];

// ---------------- asm helpers ----------------
__device__ __forceinline__ uint32_t smem_u32(const void* p) {
    uint32_t a;
    asm("{ .reg .u64 t; cvta.to.shared.u64 t, %1; cvt.u32.u64 %0, t; }"
        : "=r"(a) : "l"(p));
    return a;
}
__device__ __forceinline__ void cp16(uint32_t dst, const void* src) {
    asm volatile("cp.async.cg.shared.global [%0], [%1], 16;"
        :: "r"(dst), "l"(src) : "memory");
}
#define CP_COMMIT() asm volatile("cp.async.commit_group;" ::: "memory")
#define CP_WAIT0()  asm volatile("cp.async.wait_group 0;" ::: "memory")

__device__ __forceinline__ void ldsm4(uint32_t* r, uint32_t addr) {
    asm volatile("ldmatrix.sync.aligned.m8n8.x4.shared.b16 {%0,%1,%2,%3}, [%4];"
        : "=r"(r[0]), "=r"(r[1]), "=r"(r[2]), "=r"(r[3]) : "r"(addr));
}
__device__ __forceinline__ void ldsm2(uint32_t* r, uint32_t addr) {
    asm volatile("ldmatrix.sync.aligned.m8n8.x2.shared.b16 {%0,%1}, [%2];"
        : "=r"(r[0]), "=r"(r[1]) : "r"(addr));
}
__device__ __forceinline__ void mma_f16(float* c, const uint32_t* a,
                                        const uint32_t* b) {
    asm volatile(
        "mma.sync.aligned.m16n8k16.row.col.f32.f16.f16.f32 "
        "{%0,%1,%2,%3}, {%4,%5,%6,%7}, {%8,%9}, {%0,%1,%2,%3};"
        : "+f"(c[0]), "+f"(c[1]), "+f"(c[2]), "+f"(c[3])
        : "r"(a[0]), "r"(a[1]), "r"(a[2]), "r"(a[3]), "r"(b[0]), "r"(b[1]));
}
__device__ __forceinline__ uint32_t w2h(int w0, int w1) {
    uint32_t l = (w0 == 0) ? 0u : ((w0 > 0) ? 0x3C00u : 0xBC00u);
    uint32_t h = (w1 == 0) ? 0u : ((w1 > 0) ? 0x3C00u : 0xBC00u);
    return l | (h << 16);
}

// ---------------- x convert pre-kernel ----------------
__global__ void conv_x_kernel(const float* __restrict__ x) {
    int i = (blockIdx.x * blockDim.x + threadIdx.x) << 2;
    float4 v = *reinterpret_cast<const float4*>(x + i);
    __half2* ph = reinterpret_cast<__half2*>(g_xh + i);
    ph[0] = __floats2half2_rn(v.x, v.y);
    ph[1] = __floats2half2_rn(v.z, v.w);
}

// ---------------- main GEMM ----------------
__global__ void __launch_bounds__(THREADS, 2)
bitnet_gemm_kernel(const int* __restrict__ qw, const float* __restrict__ scale,
                   const float* __restrict__ bias, float* __restrict__ out) {
    extern __shared__ char smem[];
    const uint32_t su = smem_u32(smem);

    const int tid = threadIdx.x, wid = tid >> 5, lane = tid & 31;
    const int n_idx = blockIdx.x >> 1, m_idx = blockIdx.x & 1;
    const int n0 = n_idx * BN, m0 = m_idx * BM;
    const int n_sz = (n_idx == N_TILES - 1) ? (N_DIM - n0) : BN;   // 80 or 48

    const int warp_m = wid & 1;        // 2 m-groups, 64 rows each
    const int warp_n = wid >> 1;       // 2 n-groups, 40 cols each
    const int nbase = warp_n * 40;
    int ntiles = (n_sz - nbase) >> 3;
    if (ntiles > 5) ntiles = 5;
    if (ntiles < 0) ntiles = 0;
    const bool full = (ntiles == 5);

    // ldmatrix per-thread offsets (row stride 144B)
    const uint32_t a_off = (uint32_t)((warp_m * 64 + (lane & 15)) * ROWB +
                                      ((lane >> 4) << 4));
    // x4 B: lanes 0-7 rows nt+0..7 @0B, 8-15 same rows @16B, 16-23 rows +8,
    // 24-31 rows +8 @16B  -> tiles [nt,k0-7],[nt,k8-15],[nt+1,...]
    const uint32_t b_off4 = (uint32_t)((nbase + ((lane >> 4) << 3) + (lane & 7)) * ROWB +
                                       (((lane >> 3) & 1) << 4));
    const uint32_t b_off2 = (uint32_t)((nbase + 32 + (lane & 7)) * ROWB +
                                       (((lane >> 3) & 1) << 4));

    // W LDG: 1280 16B-chunks (80 rows x 16), 10/thread; kc = tid&15,
    // rows (tid>>4) + 8j.
    const int w_kc = tid & 15, w_row0 = tid >> 4;
    const int* wbase = qw + (size_t)n0 * K_DIM + w_kc * 4;
    int woff[10];
#pragma unroll
    for (int j = 0; j < 10; ++j) {
        int row = w_row0 + 8 * j;
        int srow = (row < n_sz) ? row : 0;     // clamp (unread if OOB)
        woff[j] = srow * K_DIM;
    }
    // A cp.async: 1024 chunks (128 rows x 8), 8/thread; kc = tid&7,
    // rows (tid>>3) + 16j.
    const int a_kc = tid & 7, a_row0 = tid >> 3;
    const __half* abase = g_xh + (size_t)(m0 + a_row0) * K_DIM + a_kc * 8;
    const uint32_t ad0 = (uint32_t)(a_row0 * ROWB + a_kc * 16);

    float acc[4][5][4];
#pragma unroll
    for (int mt = 0; mt < 4; ++mt)
#pragma unroll
        for (int nt = 0; nt < 5; ++nt)
#pragma unroll
            for (int r = 0; r < 4; ++r) acc[mt][nt][r] = 0.0f;

    int wreg[40];

    auto ldgW = [&](int k0) {
#pragma unroll
        for (int j = 0; j < 10; ++j) {
            asm volatile("ld.global.cs.v4.u32 {%0,%1,%2,%3}, [%4];"
                : "=r"(*(uint32_t*)&wreg[4*j]),   "=r"(*(uint32_t*)&wreg[4*j+1]),
                  "=r"(*(uint32_t*)&wreg[4*j+2]), "=r"(*(uint32_t*)&wreg[4*j+3])
                : "l"(wbase + woff[j] + k0));
        }
    };
    auto cpA = [&](int s, int k0) {
        const uint32_t st = su + (uint32_t)(s * STAGE_BYTES);
#pragma unroll
        for (int j = 0; j < 8; ++j)
            cp16(st + A_OFF + ad0 + (uint32_t)(j * 16 * ROWB),
                 abase + (size_t)j * 16 * K_DIM + k0);
    };

    // ---- prologue ----
    ldgW(0);
    cpA(0, 0);
    CP_COMMIT();

#pragma unroll 1
    for (int it = 0; it < KITERS; ++it) {
        const int cur = it & 1;
        const uint32_t st = su + (uint32_t)(cur * STAGE_BYTES);

        // STS W(it) from regs (ternary -> fp16)
#pragma unroll
        for (int j = 0; j < 10; ++j) {
            int row = w_row0 + 8 * j;
            uint32_t p0 = w2h(wreg[4*j],   wreg[4*j+1]);
            uint32_t p1 = w2h(wreg[4*j+2], wreg[4*j+3]);
            asm volatile("st.shared.v2.b32 [%0], {%1,%2};"
                :: "r"(st + B_OFF + (uint32_t)(row * ROWB + w_kc * 8)),
                   "r"(p0), "r"(p1) : "memory");
        }
        if (it + 1 < KITERS) ldgW((it + 1) * BK);   // covered by compute phase
        CP_WAIT0();                                 // A(it) landed
        __syncthreads();
        if (it + 1 < KITERS) { cpA(cur ^ 1, (it + 1) * BK); CP_COMMIT(); }

        // ---- compute BK=64: 4 k16 steps, frag double-buffer ----
        uint32_t af[2][4][4], bf[2][5][2];

        auto load_frags = [&](int ks, int buf) {
            const uint32_t ksb = (uint32_t)(ks * 32);
            if (full) {
                ldsm4(&bf[buf][0][0], st + B_OFF + b_off4 + ksb);
                ldsm4(&bf[buf][2][0], st + B_OFF + b_off4 + 16 * ROWB + ksb);
                ldsm2(&bf[buf][4][0], st + B_OFF + b_off2 + ksb);
            } else {
#pragma unroll
                for (int nt = 0; nt < 5; ++nt)
                    if (nt < ntiles)
                        ldsm2(&bf[buf][nt][0], st + B_OFF +
                              (uint32_t)((nbase + nt * 8 + (lane & 7)) * ROWB +
                                         (((lane >> 3) & 1) << 4)) + ksb);
            }
#pragma unroll
            for (int mt = 0; mt < 4; ++mt)
                ldsm4(af[buf][mt],
                      st + A_OFF + a_off + (uint32_t)(mt * 16 * ROWB) + ksb);
        };

        load_frags(0, 0);
#pragma unroll
        for (int ks = 0; ks < 4; ++ks) {
            const int buf = ks & 1;
            if (ks < 3) load_frags(ks + 1, buf ^ 1);
#pragma unroll
            for (int mt = 0; mt < 4; ++mt)
#pragma unroll
                for (int nt = 0; nt < 5; ++nt)
                    if (nt < ntiles) mma_f16(acc[mt][nt], af[buf][mt], bf[buf][nt]);
        }
        // single barrier per iter: next iter's STS/cpA hit the other buffer,
        // ordered against compute(it-1) by the barrier above.
    }

    // ---- epilogue: scale/bias + store ----
    const int row_base = m0 + warp_m * 64 + (lane >> 2);
    const int col_base = n0 + nbase + ((lane & 3) << 1);
#pragma unroll
    for (int mt = 0; mt < 4; ++mt) {
#pragma unroll
        for (int nt = 0; nt < 5; ++nt) {
            if (nt < ntiles) {
                int col = col_base + nt * 8;
                float2 sc = *reinterpret_cast<const float2*>(scale + col);
                float2 bs = *reinterpret_cast<const float2*>(bias + col);
                int r0 = row_base + mt * 16;
                float2 o0, o1;
                o0.x = acc[mt][nt][0] * sc.x + bs.x;
                o0.y = acc[mt][nt][1] * sc.y + bs.y;
                o1.x = acc[mt][nt][2] * sc.x + bs.x;
                o1.y = acc[mt][nt][3] * sc.y + bs.y;
                *reinterpret_cast<float2*>(out + (size_t)r0 * N_DIM + col) = o0;
                *reinterpret_cast<float2*>(out + (size_t)(r0 + 8) * N_DIM + col) = o1;
            }
        }
    }
}

// ---------------- launch ----------------
extern "C" void kernel_launch(void* const* d_in, const int* in_sizes, int n_in,
                              void* d_out, int out_size) {
    const float* x = nullptr; const int* qw = nullptr;
    const float* scale = nullptr; const float* bias = nullptr;
    for (int i = 0; i < n_in; ++i) {
        if (in_sizes[i] == M_TOK * K_DIM) x = (const float*)d_in[i];
        else if (in_sizes[i] == N_DIM * K_DIM) qw = (const int*)d_in[i];
        else if (in_sizes[i] == N_DIM) {
            if (!scale) scale = (const float*)d_in[i];
            else bias = (const float*)d_in[i];
        }
    }
    float* out = (float*)d_out;

    cudaFuncSetAttribute(bitnet_gemm_kernel,
                         cudaFuncAttributeMaxDynamicSharedMemorySize, SMEM_ALLOC);

    conv_x_kernel<<<(M_TOK * K_DIM) / (256 * 4), 256>>>(x);
    bitnet_gemm_kernel<<<GRID, THREADS, SMEM_ALLOC>>>(qw, scale, bias, out);
}

// round 9
// speedup vs baseline: 1.1002x; 1.0102x over previous
#include <cuda_runtime.h>
#include <cuda_fp16.h>
#include <cstdint>
#include <cstddef>

// out[256,11008] = x[256,4096] @ W[11008,4096]^T * scale + bias, W ternary i32.
// fp16 mma.sync m16n8k16 single pass, fp32 accum (rel_err ~2e-4 << 1e-3).
// BM=128 BN=80 BK=64. CTA = 128 thr / 4 warps (2m x 2n), warp tile 64x40.
// 276 CTAs, 2 CTAs/SM. A: cp.async, 3 stages, wait_group 1. W: LDG.128 ->
// PRMT ternary->fp16 -> STS.128, 2 B stages. One barrier/iter. Co-resident
// CTA pairs start K at opposite phase (anti-phase overlap).

#define M_TOK   256
#define K_DIM   4096
#define N_DIM   11008
#define BM      128
#define BN      80
#define BK      64
#define KITERS  (K_DIM / BK)          // 64
#define THREADS 128
#define N_TILES 138
#define GRID    (2 * N_TILES)         // 276

#define ROWB     144                  // row pad: conflict-free ldmatrix
#define A_STAGE  18432                // 128 x 144
#define B_STAGE  11520                // 80 x 144
#define B_BASE   (3 * A_STAGE)        // 55296
#define SMEM_ALLOC (B_BASE + 2 * B_STAGE)   // 78336

__device__ __half g_xh[M_TOK * K_DIM];

// ---------------- asm helpers ----------------
__device__ __forceinline__ uint32_t smem_u32(const void* p) {
    uint32_t a;
    asm("{ .reg .u64 t; cvta.to.shared.u64 t, %1; cvt.u32.u64 %0, t; }"
        : "=r"(a) : "l"(p));
    return a;
}
__device__ __forceinline__ void cp16(uint32_t dst, const void* src) {
    asm volatile("cp.async.cg.shared.global [%0], [%1], 16;"
        :: "r"(dst), "l"(src) : "memory");
}
#define CP_COMMIT() asm volatile("cp.async.commit_group;" ::: "memory")
#define CP_WAIT1()  asm volatile("cp.async.wait_group 1;" ::: "memory")

__device__ __forceinline__ void ldsm4(uint32_t* r, uint32_t addr) {
    asm volatile("ldmatrix.sync.aligned.m8n8.x4.shared.b16 {%0,%1,%2,%3}, [%4];"
        : "=r"(r[0]), "=r"(r[1]), "=r"(r[2]), "=r"(r[3]) : "r"(addr));
}
__device__ __forceinline__ void ldsm2(uint32_t* r, uint32_t addr) {
    asm volatile("ldmatrix.sync.aligned.m8n8.x2.shared.b16 {%0,%1}, [%2];"
        : "=r"(r[0]), "=r"(r[1]) : "r"(addr));
}
__device__ __forceinline__ void mma_f16(float* c, const uint32_t* a,
                                        const uint32_t* b) {
    asm volatile(
        "mma.sync.aligned.m16n8k16.row.col.f32.f16.f16.f32 "
        "{%0,%1,%2,%3}, {%4,%5,%6,%7}, {%8,%9}, {%0,%1,%2,%3};"
        : "+f"(c[0]), "+f"(c[1]), "+f"(c[2]), "+f"(c[3])
        : "r"(a[0]), "r"(a[1]), "r"(a[2]), "r"(a[3]), "r"(b[0]), "r"(b[1]));
}
// two ternary int32 -> packed fp16x2 {0,+-1}: 4 ops (PRMT, AND, IMAD, LOP3)
__device__ __forceinline__ uint32_t w2h2(uint32_t w0, uint32_t w1) {
    uint32_t c = __byte_perm(w0, w1, 0x5410);   // lo16(w0) | lo16(w1)<<16
    return ((c & 0x00010001u) * 0x3C00u) | (c & 0x80008000u);
}

// ---------------- x convert pre-kernel ----------------
__global__ void conv_x_kernel(const float* __restrict__ x) {
    int i = (blockIdx.x * blockDim.x + threadIdx.x) << 2;
    float4 v = *reinterpret_cast<const float4*>(x + i);
    __half2* ph = reinterpret_cast<__half2*>(g_xh + i);
    ph[0] = __floats2half2_rn(v.x, v.y);
    ph[1] = __floats2half2_rn(v.z, v.w);
}

// ---------------- main GEMM ----------------
__global__ void __launch_bounds__(THREADS, 2)
bitnet_gemm_kernel(const int* __restrict__ qw, const float* __restrict__ scale,
                   const float* __restrict__ bias, float* __restrict__ out) {
    extern __shared__ char smem[];
    const uint32_t su = smem_u32(smem);

    const int tid = threadIdx.x, wid = tid >> 5, lane = tid & 31;
    const int n_idx = blockIdx.x >> 1, m_idx = blockIdx.x & 1;
    const int n0 = n_idx * BN, m0 = m_idx * BM;
    const int n_sz = (n_idx == N_TILES - 1) ? (N_DIM - n0) : BN;   // 80 or 48
    // anti-phase: the co-resident partner (bid +/-148) starts half-way
    const int stag = (blockIdx.x >= 148) ? (KITERS / 2) : 0;

    const int warp_m = wid & 1;        // 2 m-groups, 64 rows each
    const int warp_n = wid >> 1;       // 2 n-groups, 40 cols each
    const int nbase = warp_n * 40;
    int ntiles = (n_sz - nbase) >> 3;
    if (ntiles > 5) ntiles = 5;
    if (ntiles < 0) ntiles = 0;
    const bool full = (ntiles == 5);

    // ldmatrix per-thread offsets (row stride 144B)
    const uint32_t a_off = (uint32_t)((warp_m * 64 + (lane & 15)) * ROWB +
                                      ((lane >> 4) << 4));
    const uint32_t b_off4 = (uint32_t)((nbase + ((lane >> 4) << 3) + (lane & 7)) * ROWB +
                                       (((lane >> 3) & 1) << 4));
    const uint32_t b_off2 = (uint32_t)((nbase + 32 + (lane & 7)) * ROWB +
                                       (((lane >> 3) & 1) << 4));

    // W LDG: thread owns kc-PAIR w_kp (32B int32 = 8 weights -> 16B fp16),
    // rows (tid>>3) + 16j, j=0..4. 2 LDG.128 + 1 STS.128 per row.
    const int w_kp = tid & 7, w_row0 = tid >> 3;
    const int* wbase = qw + (size_t)n0 * K_DIM + w_kp * 8;
    int woff[5];
#pragma unroll
    for (int j = 0; j < 5; ++j) {
        int row = w_row0 + 16 * j;
        int srow = (row < n_sz) ? row : 0;     // clamp (unread if OOB)
        woff[j] = srow * K_DIM;
    }
    // A cp.async: 1024 chunks (128 rows x 8), 8/thread
    const int a_kc = tid & 7, a_row0 = tid >> 3;
    const __half* abase = g_xh + (size_t)(m0 + a_row0) * K_DIM + a_kc * 8;
    const uint32_t ad0 = (uint32_t)(a_row0 * ROWB + a_kc * 16);

    float acc[4][5][4];
#pragma unroll
    for (int mt = 0; mt < 4; ++mt)
#pragma unroll
        for (int nt = 0; nt < 5; ++nt)
#pragma unroll
            for (int r = 0; r < 4; ++r) acc[mt][nt][r] = 0.0f;

    uint32_t wreg[40];

    auto kof = [&](int i) { return ((i + stag) & (KITERS - 1)) * BK; };

    auto ldgW = [&](int k0) {
#pragma unroll
        for (int j = 0; j < 5; ++j) {
            const int* s = wbase + woff[j] + k0;
            asm volatile("ld.global.cs.v4.u32 {%0,%1,%2,%3}, [%4];"
                : "=r"(wreg[8*j]),   "=r"(wreg[8*j+1]),
                  "=r"(wreg[8*j+2]), "=r"(wreg[8*j+3]) : "l"(s));
            asm volatile("ld.global.cs.v4.u32 {%0,%1,%2,%3}, [%4];"
                : "=r"(wreg[8*j+4]), "=r"(wreg[8*j+5]),
                  "=r"(wreg[8*j+6]), "=r"(wreg[8*j+7]) : "l"(s + 4));
        }
    };
    auto cpA = [&](int s, int k0) {
        const uint32_t st = su + (uint32_t)(s * A_STAGE);
#pragma unroll
        for (int j = 0; j < 8; ++j)
            cp16(st + ad0 + (uint32_t)(j * 16 * ROWB),
                 abase + (size_t)j * 16 * K_DIM + k0);
    };

    // ---- prologue: 2 A stages in flight ----
    ldgW(kof(0));
    cpA(0, kof(0)); CP_COMMIT();
    cpA(1, kof(1)); CP_COMMIT();

#pragma unroll 1
    for (int it = 0; it < KITERS; ++it) {
        const int curB = it & 1;
        const uint32_t stA = su + (uint32_t)((it % 3) * A_STAGE);
        const uint32_t stB = su + (uint32_t)(B_BASE + curB * B_STAGE);

        // STS W(it): 5 x STS.128 (safe pre-barrier: last reader of this B buf
        // was compute(it-2), ordered by barrier(it-1))
#pragma unroll
        for (int j = 0; j < 5; ++j) {
            int row = w_row0 + 16 * j;
            uint32_t p0 = w2h2(wreg[8*j],   wreg[8*j+1]);
            uint32_t p1 = w2h2(wreg[8*j+2], wreg[8*j+3]);
            uint32_t p2 = w2h2(wreg[8*j+4], wreg[8*j+5]);
            uint32_t p3 = w2h2(wreg[8*j+6], wreg[8*j+7]);
            asm volatile("st.shared.v4.b32 [%0], {%1,%2,%3,%4};"
                :: "r"(stB + (uint32_t)(row * ROWB + w_kp * 16)),
                   "r"(p0), "r"(p1), "r"(p2), "r"(p3) : "memory");
        }
        if (it + 1 < KITERS) ldgW(kof(it + 1));     // covered by compute phase
        CP_WAIT1();                                 // A(it) landed; A(it+1) may fly
        __syncthreads();
        if (it + 2 < KITERS) cpA((it + 2) % 3, kof(it + 2));
        CP_COMMIT();                                // always commit (group count)

        // ---- compute BK=64: 4 k16 steps, frag double-buffer ----
        uint32_t af[2][4][4], bf[2][5][2];
        auto load_frags = [&](int ks, int buf) {
            const uint32_t ksb = (uint32_t)(ks * 32);
            if (full) {
                ldsm4(&bf[buf][0][0], stB + b_off4 + ksb);
                ldsm4(&bf[buf][2][0], stB + b_off4 + 16 * ROWB + ksb);
                ldsm2(&bf[buf][4][0], stB + b_off2 + ksb);
            } else {
#pragma unroll
                for (int nt = 0; nt < 5; ++nt)
                    if (nt < ntiles)
                        ldsm2(&bf[buf][nt][0], stB +
                              (uint32_t)((nbase + nt * 8 + (lane & 7)) * ROWB +
                                         (((lane >> 3) & 1) << 4)) + ksb);
            }
#pragma unroll
            for (int mt = 0; mt < 4; ++mt)
                ldsm4(af[buf][mt], stA + a_off + (uint32_t)(mt * 16 * ROWB) + ksb);
        };

        load_frags(0, 0);
#pragma unroll
        for (int ks = 0; ks < 4; ++ks) {
            const int buf = ks & 1;
            if (ks < 3) load_frags(ks + 1, buf ^ 1);
#pragma unroll
            for (int mt = 0; mt < 4; ++mt)
#pragma unroll
                for (int nt = 0; nt < 5; ++nt)
                    if (nt < ntiles) mma_f16(acc[mt][nt], af[buf][mt], bf[buf][nt]);
        }
    }

    // ---- epilogue: scale/bias + store ----
    const int row_base = m0 + warp_m * 64 + (lane >> 2);
    const int col_base = n0 + nbase + ((lane & 3) << 1);
#pragma unroll
    for (int mt = 0; mt < 4; ++mt) {
#pragma unroll
        for (int nt = 0; nt < 5; ++nt) {
            if (nt < ntiles) {
                int col = col_base + nt * 8;
                float2 sc = *reinterpret_cast<const float2*>(scale + col);
                float2 bs = *reinterpret_cast<const float2*>(bias + col);
                int r0 = row_base + mt * 16;
                float2 o0, o1;
                o0.x = acc[mt][nt][0] * sc.x + bs.x;
                o0.y = acc[mt][nt][1] * sc.y + bs.y;
                o1.x = acc[mt][nt][2] * sc.x + bs.x;
                o1.y = acc[mt][nt][3] * sc.y + bs.y;
                *reinterpret_cast<float2*>(out + (size_t)r0 * N_DIM + col) = o0;
                *reinterpret_cast<float2*>(out + (size_t)(r0 + 8) * N_DIM + col) = o1;
            }
        }
    }
}

// ---------------- launch ----------------
extern "C" void kernel_launch(void* const* d_in, const int* in_sizes, int n_in,
                              void* d_out, int out_size) {
    const float* x = nullptr; const int* qw = nullptr;
    const float* scale = nullptr; const float* bias = nullptr;
    for (int i = 0; i < n_in; ++i) {
        if (in_sizes[i] == M_TOK * K_DIM) x = (const float*)d_in[i];
        else if (in_sizes[i] == N_DIM * K_DIM) qw = (const int*)d_in[i];
        else if (in_sizes[i] == N_DIM) {
            if (!scale) scale = (const float*)d_in[i];
            else bias = (const float*)d_in[i];
        }
    }
    float* out = (float*)d_out;

    cudaFuncSetAttribute(bitnet_gemm_kernel,
                         cudaFuncAttributeMaxDynamicSharedMemorySize, SMEM_ALLOC);

    conv_x_kernel<<<(M_TOK * K_DIM) / (256 * 4), 256>>>(x);
    bitnet_gemm_kernel<<<GRID, THREADS, SMEM_ALLOC>>>(qw, scale, bias, out);
}